// round 6
// baseline (speedup 1.0000x reference)
#include <cuda_runtime.h>
#include <cuda_bf16.h>

// Grid shape fixed for this problem instance.
#define GH 704
#define GW 704
#define GD 64
#define BLOCK 256
#define XSPLIT 352   // pass 0: x0 in [0,352]; pass 1: x0 in [353,703]

__device__ float g_sum;          // zero at load; reset by finalize each launch
__device__ unsigned g_count;

__device__ __forceinline__ float read_grid_factor(const void* p) {
    // grid_factor may be stored as int32 (10) or float32 (10.0f).
    int bits = *(const int*)p;
    if (bits > 0 && bits < 1000000) return (float)bits;
    return __int_as_float(bits);
}

struct Corner {
    int b00, b01, b10, b11;   // row bases (int: grid < 2^31 elems)
    int z0, z1;
    int x0;
    float wx, wy, wz;
};

__device__ __forceinline__ Corner setup(float px, float py, float pz,
                                        float gx, float gy, float gz, float gf)
{
    Corner c;
    float sx = fminf(fmaxf((px - gx) * gf, 0.0f), (float)(GH - 1));
    float sy = fminf(fmaxf((py - gy) * gf, 0.0f), (float)(GW - 1));
    float sz = fminf(fmaxf((pz - gz) * gf, 0.0f), (float)(GD - 1));

    int x0 = (int)floorf(sx); int x1 = min(x0 + 1, GH - 1);
    int y0 = (int)floorf(sy); int y1 = min(y0 + 1, GW - 1);
    c.z0 = (int)floorf(sz);   c.z1 = min(c.z0 + 1, GD - 1);

    c.x0 = x0;
    c.wx = sx - (float)x0;
    c.wy = sy - (float)y0;
    c.wz = sz - (float)c.z0;

    c.b00 = (x0 * GW + y0) * GD;
    c.b01 = (x0 * GW + y1) * GD;
    c.b10 = (x1 * GW + y0) * GD;
    c.b11 = (x1 * GW + y1) * GD;
    return c;
}

__device__ __forceinline__ float gather_lerp(const float* __restrict__ grid, const Corner& a)
{
    float c000 = __ldg(&grid[a.b00 + a.z0]);
    float c001 = __ldg(&grid[a.b00 + a.z1]);
    float c010 = __ldg(&grid[a.b01 + a.z0]);
    float c011 = __ldg(&grid[a.b01 + a.z1]);
    float c100 = __ldg(&grid[a.b10 + a.z0]);
    float c101 = __ldg(&grid[a.b10 + a.z1]);
    float c110 = __ldg(&grid[a.b11 + a.z0]);
    float c111 = __ldg(&grid[a.b11 + a.z1]);

    float c00 = c000 + (c001 - c000) * a.wz;
    float c01 = c010 + (c011 - c010) * a.wz;
    float c10 = c100 + (c101 - c100) * a.wz;
    float c11 = c110 + (c111 - c110) * a.wz;
    float c0  = c00  + (c01  - c00 ) * a.wy;
    float c1  = c10  + (c11  - c10 ) * a.wy;
    return c0 + (c1 - c0) * a.wx;
}

__global__ __launch_bounds__(BLOCK)
void dt_loss_pass(const float* __restrict__ pc1,
                  const float* __restrict__ flow,
                  const float* __restrict__ grid,
                  const float* __restrict__ gmin,
                  const void*  __restrict__ gfac,
                  float* __restrict__ out,
                  int N, int off, int stride,
                  int xlo, int xhi, int is_final)
{
    const float gf = read_grid_factor(gfac);
    const float gx = __ldg(&gmin[0]);
    const float gy = __ldg(&gmin[1]);
    const float gz = __ldg(&gmin[2]);

    int i0 = blockIdx.x * BLOCK + threadIdx.x;
    int i1 = i0 + stride;

    float acc = 0.0f;

    #pragma unroll
    for (int pass = 0; pass < 2; pass++) {
        int i = (pass == 0) ? i0 : i1;
        if (i >= N) continue;

        // Streaming loads (evict-first) — protect slab's L2 residency.
        float px = __ldcs(&pc1[3 * i + 0]) + __ldcs(&flow[3 * i + 0]);
        float py = __ldcs(&pc1[3 * i + 1]) + __ldcs(&flow[3 * i + 1]);
        float pz = __ldcs(&pc1[3 * i + 2]) + __ldcs(&flow[3 * i + 2]);

        Corner a = setup(px, py, pz, gx, gy, gz, gf);

        if (a.x0 >= xlo && a.x0 <= xhi) {
            float v = gather_lerp(grid, a);
            __stcs(&out[off + i], v);
            acc += v;
        }
    }

    // ---- block reduction ----
    __shared__ float warp_sums[BLOCK / 32];
    __shared__ bool  is_last;
    int lane = threadIdx.x & 31;
    int wid  = threadIdx.x >> 5;

    #pragma unroll
    for (int d = 16; d > 0; d >>= 1)
        acc += __shfl_down_sync(0xFFFFFFFFu, acc, d);
    if (lane == 0) warp_sums[wid] = acc;
    __syncthreads();

    if (wid == 0) {
        float s = (lane < BLOCK / 32) ? warp_sums[lane] : 0.0f;
        #pragma unroll
        for (int d = 4; d > 0; d >>= 1)
            s += __shfl_down_sync(0xFFFFFFFFu, s, d);
        if (lane == 0) {
            atomicAdd(&g_sum, s);
            if (is_final) {
                __threadfence();
                unsigned prev = atomicAdd(&g_count, 1u);
                is_last = (prev == gridDim.x - 1);
            } else {
                is_last = false;
            }
        }
    }
    __syncthreads();

    // Last block of the final pass: write mean, reset for next graph replay.
    if (is_last && threadIdx.x == 0) {
        float total = g_sum;
        if (off > 0) out[0] = total / (float)N;
        g_sum = 0.0f;
        g_count = 0u;
    }
}

extern "C" void kernel_launch(void* const* d_in, const int* in_sizes, int n_in,
                              void* d_out, int out_size)
{
    const float* pc1  = (const float*)d_in[0];
    const float* flow = (const float*)d_in[1];
    const float* grid = (const float*)d_in[2];
    const float* gmin = (const float*)d_in[3];
    const void*  gfac = d_in[4];
    float* out = (float*)d_out;

    int N = in_sizes[0] / 3;
    int off = out_size - N;      // 1 if [mean, dist...], 0 if just [dist...]
    if (off < 0) off = 0;

    int blocks = (N + 2 * BLOCK - 1) / (2 * BLOCK);
    int stride = blocks * BLOCK;

    // Pass 0: lower x slab (~63 MB of grid, fits L2 with room to spare).
    dt_loss_pass<<<blocks, BLOCK>>>(pc1, flow, grid, gmin, gfac, out,
                                    N, off, stride, 0, XSPLIT, 0);
    // Pass 1: upper x slab + finalize.
    dt_loss_pass<<<blocks, BLOCK>>>(pc1, flow, grid, gmin, gfac, out,
                                    N, off, stride, XSPLIT + 1, GH - 1, 1);
}